// round 1
// baseline (speedup 1.0000x reference)
#include <cuda_runtime.h>

#define D_MODEL 1024
#define NHEAD   16
#define HDIM    64
#define BATCH   4
#define SEQ     2048
#define NTOK    (BATCH*SEQ)

// Scratch: projected Q/K/V and pre-Wo attention output. Static __device__
// arrays (allocation-free, allowed by harness rules).
__device__ float g_q[(size_t)NTOK * D_MODEL];
__device__ float g_k[(size_t)NTOK * D_MODEL];
__device__ float g_v[(size_t)NTOK * D_MODEL];
__device__ float g_att[(size_t)NTOK * D_MODEL];

// ---------------------------------------------------------------------------
// C[M,N] = A[M,K] @ W[N,K]^T + bias[N]   (NT GEMM: both K-contiguous)
// 128x128 tile, BK=8, 256 threads, 8x8 micro-tile per thread.
// M,N multiples of 128; K multiple of 8 (holds for all 4 call sites).
// ---------------------------------------------------------------------------
__global__ __launch_bounds__(256, 2)
void gemm_nt_bias(const float* __restrict__ A, const float* __restrict__ W,
                  const float* __restrict__ bias, float* __restrict__ C,
                  int M, int N, int K)
{
    __shared__ float As[8][128];
    __shared__ float Bs[8][128];

    const int tid = threadIdx.x;
    const int bm = blockIdx.y * 128;
    const int bn = blockIdx.x * 128;

    // global->smem loaders: thread loads one float4 of A and one of W
    const int lr = tid >> 1;          // 0..127 tile row
    const int lc = (tid & 1) * 4;     // 0 or 4 within BK=8
    const float* Ap = A + (size_t)(bm + lr) * K + lc;
    const float* Wp = W + (size_t)(bn + lr) * K + lc;

    const int tm0 = (tid >> 4) * 8;   // 16 row-groups * 8
    const int tn0 = (tid & 15) * 8;   // 16 col-groups * 8

    float acc[8][8];
#pragma unroll
    for (int i = 0; i < 8; i++)
#pragma unroll
        for (int j = 0; j < 8; j++) acc[i][j] = 0.f;

    for (int k0 = 0; k0 < K; k0 += 8) {
        float4 a4 = *(const float4*)(Ap + k0);
        float4 b4 = *(const float4*)(Wp + k0);
        __syncthreads();   // previous iteration's smem reads complete
        As[lc + 0][lr] = a4.x; As[lc + 1][lr] = a4.y;
        As[lc + 2][lr] = a4.z; As[lc + 3][lr] = a4.w;
        Bs[lc + 0][lr] = b4.x; Bs[lc + 1][lr] = b4.y;
        Bs[lc + 2][lr] = b4.z; Bs[lc + 3][lr] = b4.w;
        __syncthreads();

#pragma unroll
        for (int kk = 0; kk < 8; kk++) {
            float a[8], b[8];
            *(float4*)&a[0] = *(const float4*)&As[kk][tm0];
            *(float4*)&a[4] = *(const float4*)&As[kk][tm0 + 4];
            *(float4*)&b[0] = *(const float4*)&Bs[kk][tn0];
            *(float4*)&b[4] = *(const float4*)&Bs[kk][tn0 + 4];
#pragma unroll
            for (int i = 0; i < 8; i++)
#pragma unroll
                for (int j = 0; j < 8; j++)
                    acc[i][j] = fmaf(a[i], b[j], acc[i][j]);
        }
    }

    float bv[8];
    *(float4*)&bv[0] = *(const float4*)&bias[bn + tn0];
    *(float4*)&bv[4] = *(const float4*)&bias[bn + tn0 + 4];
#pragma unroll
    for (int i = 0; i < 8; i++) {
        float out[8];
#pragma unroll
        for (int j = 0; j < 8; j++) out[j] = acc[i][j] + bv[j];
        float* Cp = C + (size_t)(bm + tm0 + i) * N + bn + tn0;
        *(float4*)&Cp[0] = *(const float4*)&out[0];
        *(float4*)&Cp[4] = *(const float4*)&out[4];
    }
}

// ---------------------------------------------------------------------------
// Flash attention, fp32. One block = (64-query tile, head, batch).
// 128 threads: thread grid (16 row-groups x 8 col-groups).
//  S-phase: 4x4 score frag per thread over a 64x32 KV tile.
//  O-phase: 4x8 output frag per thread (Dh=64 split over 8 col-groups).
// Q/K held transposed in smem with padded strides so all hot reads are
// aligned float4 with <=2 crossbar phases per warp instruction.
// ---------------------------------------------------------------------------
__global__ __launch_bounds__(128)
void attn_fwd(const float* __restrict__ Qg, const float* __restrict__ Kg,
              const float* __restrict__ Vg, float* __restrict__ Og)
{
    __shared__ float Qt[64][68];   // [d][m]  (17.4 KB) stride 68: 272B %16==0
    __shared__ float Kt[64][36];   // [d][n]  ( 9.2 KB) stride 36: 144B %16==0
    __shared__ float Vs[32][64];   // [j][d]  ( 8.0 KB)
    __shared__ float Pt[32][68];   // [j][m]  ( 8.7 KB)   total ~43.3 KB

    const int t  = threadIdx.x;
    const int mt = blockIdx.x;
    const int h  = blockIdx.y;
    const int b  = blockIdx.z;
    const int cg = t & 7;          // col group (8 lanes share a row -> shfl 1,2,4)
    const int rg = t >> 3;         // row group 0..15
    const int tm0 = rg * 4;        // 4 query rows per thread
    const int tnS = cg * 4;        // 4 key cols per thread (S-phase)
    const int td0 = cg * 8;        // 8 head dims per thread (O-phase)

    const float* Qb = Qg + ((size_t)(b * SEQ) + mt * 64) * D_MODEL + h * HDIM;
    const float* Kb = Kg + (size_t)(b * SEQ) * D_MODEL + h * HDIM;
    const float* Vb = Vg + (size_t)(b * SEQ) * D_MODEL + h * HDIM;

    // Load Q tile transposed: Qt[d][m]
    for (int i = t; i < 64 * 16; i += 128) {
        int m = i >> 4, f4 = i & 15;
        float4 v = *(const float4*)(Qb + (size_t)m * D_MODEL + f4 * 4);
        Qt[f4 * 4 + 0][m] = v.x; Qt[f4 * 4 + 1][m] = v.y;
        Qt[f4 * 4 + 2][m] = v.z; Qt[f4 * 4 + 3][m] = v.w;
    }

    float mrow[4], lrow[4], o[4][8];
#pragma unroll
    for (int r = 0; r < 4; r++) {
        mrow[r] = -1e30f; lrow[r] = 0.f;
#pragma unroll
        for (int d = 0; d < 8; d++) o[r][d] = 0.f;
    }

    const float SC = 0.125f;  // 1/sqrt(64)

    for (int kt = 0; kt < SEQ / 32; kt++) {
        __syncthreads();   // prev iteration's Pt/Vs/Kt reads complete
        const float* Kp = Kb + (size_t)kt * 32 * D_MODEL;
        const float* Vp = Vb + (size_t)kt * 32 * D_MODEL;
        for (int i = t; i < 32 * 16; i += 128) {
            int n = i >> 4, f4 = i & 15;
            float4 kv = *(const float4*)(Kp + (size_t)n * D_MODEL + f4 * 4);
            Kt[f4 * 4 + 0][n] = kv.x; Kt[f4 * 4 + 1][n] = kv.y;
            Kt[f4 * 4 + 2][n] = kv.z; Kt[f4 * 4 + 3][n] = kv.w;
            float4 vv = *(const float4*)(Vp + (size_t)n * D_MODEL + f4 * 4);
            *(float4*)&Vs[n][f4 * 4] = vv;
        }
        __syncthreads();

        // S = Q @ K^T  (raw scores; scale folded into exp)
        float s[4][4];
#pragma unroll
        for (int r = 0; r < 4; r++)
#pragma unroll
            for (int j = 0; j < 4; j++) s[r][j] = 0.f;

#pragma unroll 8
        for (int d = 0; d < 64; d++) {
            float a[4], bb[4];
            *(float4*)a  = *(const float4*)&Qt[d][tm0];
            *(float4*)bb = *(const float4*)&Kt[d][tnS];
#pragma unroll
            for (int r = 0; r < 4; r++)
#pragma unroll
                for (int j = 0; j < 4; j++)
                    s[r][j] = fmaf(a[r], bb[j], s[r][j]);
        }

        // Online softmax (row reductions across the 8 col-group lanes)
        float p[4][4];
#pragma unroll
        for (int r = 0; r < 4; r++) {
            float mx = fmaxf(fmaxf(s[r][0], s[r][1]), fmaxf(s[r][2], s[r][3]));
            mx = fmaxf(mx, __shfl_xor_sync(0xffffffffu, mx, 1));
            mx = fmaxf(mx, __shfl_xor_sync(0xffffffffu, mx, 2));
            mx = fmaxf(mx, __shfl_xor_sync(0xffffffffu, mx, 4));
            float mn   = fmaxf(mrow[r], mx);
            float corr = __expf((mrow[r] - mn) * SC);
            mrow[r] = mn;
            float rs = 0.f;
#pragma unroll
            for (int j = 0; j < 4; j++) {
                p[r][j] = __expf((s[r][j] - mn) * SC);
                rs += p[r][j];
            }
            rs += __shfl_xor_sync(0xffffffffu, rs, 1);
            rs += __shfl_xor_sync(0xffffffffu, rs, 2);
            rs += __shfl_xor_sync(0xffffffffu, rs, 4);
            lrow[r] = lrow[r] * corr + rs;
#pragma unroll
            for (int d = 0; d < 8; d++) o[r][d] *= corr;
        }

        // P to smem transposed: Pt[j][m]
#pragma unroll
        for (int j = 0; j < 4; j++)
#pragma unroll
            for (int r = 0; r < 4; r++)
                Pt[tnS + j][tm0 + r] = p[r][j];
        __syncthreads();

        // O += P @ V
#pragma unroll 4
        for (int j = 0; j < 32; j++) {
            float a[4], vv[8];
            *(float4*)a      = *(const float4*)&Pt[j][tm0];
            *(float4*)&vv[0] = *(const float4*)&Vs[j][td0];
            *(float4*)&vv[4] = *(const float4*)&Vs[j][td0 + 4];
#pragma unroll
            for (int r = 0; r < 4; r++)
#pragma unroll
                for (int d = 0; d < 8; d++)
                    o[r][d] = fmaf(a[r], vv[d], o[r][d]);
        }
    }

    // Epilogue: O /= l, write in [B,S,H*Dh] layout (matches reference reshape)
#pragma unroll
    for (int r = 0; r < 4; r++) {
        float inv = 1.f / lrow[r];
        float out[8];
#pragma unroll
        for (int d = 0; d < 8; d++) out[d] = o[r][d] * inv;
        float* Op = Og + ((size_t)(b * SEQ) + mt * 64 + tm0 + r) * D_MODEL
                    + h * HDIM + td0;
        *(float4*)&Op[0] = *(const float4*)&out[0];
        *(float4*)&Op[4] = *(const float4*)&out[4];
    }
}

// ---------------------------------------------------------------------------
extern "C" void kernel_launch(void* const* d_in, const int* in_sizes, int n_in,
                              void* d_out, int out_size)
{
    const float* q  = (const float*)d_in[0];
    const float* k  = (const float*)d_in[1];
    const float* v  = (const float*)d_in[2];
    const float* Wq = (const float*)d_in[3];
    const float* bq = (const float*)d_in[4];
    const float* Wk = (const float*)d_in[5];
    const float* bk = (const float*)d_in[6];
    const float* Wv = (const float*)d_in[7];
    const float* bv = (const float*)d_in[8];
    const float* Wo = (const float*)d_in[9];
    const float* bo = (const float*)d_in[10];
    float* out = (float*)d_out;

    float *gq, *gk, *gv, *ga;
    cudaGetSymbolAddress((void**)&gq, g_q);
    cudaGetSymbolAddress((void**)&gk, g_k);
    cudaGetSymbolAddress((void**)&gv, g_v);
    cudaGetSymbolAddress((void**)&ga, g_att);

    dim3 ggrid(D_MODEL / 128, NTOK / 128);   // (8, 64)
    gemm_nt_bias<<<ggrid, 256>>>(q, Wq, bq, gq, NTOK, D_MODEL, D_MODEL);
    gemm_nt_bias<<<ggrid, 256>>>(k, Wk, bk, gk, NTOK, D_MODEL, D_MODEL);
    gemm_nt_bias<<<ggrid, 256>>>(v, Wv, bv, gv, NTOK, D_MODEL, D_MODEL);

    attn_fwd<<<dim3(SEQ / 64, NHEAD, BATCH), 128>>>(gq, gk, gv, ga);

    gemm_nt_bias<<<ggrid, 256>>>(ga, Wo, bo, out, NTOK, D_MODEL, D_MODEL);
}

// round 3
// speedup vs baseline: 1.4411x; 1.4411x over previous
#include <cuda_runtime.h>
#include <cuda_bf16.h>
#include <cstdint>

#define D_MODEL 1024
#define NHEAD   16
#define HDIM    64
#define BATCH   4
#define SEQ     2048
#define NTOK    (BATCH*SEQ)

// Scratch (allocation-free per harness rules)
__device__ float g_q[(size_t)NTOK * D_MODEL];
__device__ float g_k[(size_t)NTOK * D_MODEL];
__device__ float g_v[(size_t)NTOK * D_MODEL];
__device__ float g_att[(size_t)NTOK * D_MODEL];

// ---------------------------------------------------------------------------
// helpers
// ---------------------------------------------------------------------------
__device__ __forceinline__ uint32_t smem_u32(const void* p) {
    uint32_t a;
    asm("{ .reg .u64 t; cvta.to.shared.u64 t, %1; cvt.u32.u64 %0, t; }"
        : "=r"(a) : "l"(p));
    return a;
}
__device__ __forceinline__ void ldm_x4(uint32_t r[4], uint32_t addr) {
    asm volatile("ldmatrix.sync.aligned.m8n8.x4.shared.b16 {%0,%1,%2,%3}, [%4];"
                 : "=r"(r[0]), "=r"(r[1]), "=r"(r[2]), "=r"(r[3]) : "r"(addr));
}
__device__ __forceinline__ void mma16816(float c[4], const uint32_t a[4],
                                         uint32_t b0, uint32_t b1) {
    asm volatile(
        "mma.sync.aligned.m16n8k16.row.col.f32.bf16.bf16.f32 "
        "{%0,%1,%2,%3}, {%4,%5,%6,%7}, {%8,%9}, {%0,%1,%2,%3};"
        : "+f"(c[0]), "+f"(c[1]), "+f"(c[2]), "+f"(c[3])
        : "r"(a[0]), "r"(a[1]), "r"(a[2]), "r"(a[3]), "r"(b0), "r"(b1));
}
// split one float4 into packed-hi (uint2) and packed-lo (uint2) bf16x4
__device__ __forceinline__ void split_f4(float4 v, uint2& hi, uint2& lo) {
    float2 p0 = make_float2(v.x, v.y), p1 = make_float2(v.z, v.w);
    __nv_bfloat162 h0 = __float22bfloat162_rn(p0);
    __nv_bfloat162 h1 = __float22bfloat162_rn(p1);
    float2 r0 = make_float2(p0.x - __low2float(h0), p0.y - __high2float(h0));
    float2 r1 = make_float2(p1.x - __low2float(h1), p1.y - __high2float(h1));
    __nv_bfloat162 l0 = __float22bfloat162_rn(r0);
    __nv_bfloat162 l1 = __float22bfloat162_rn(r1);
    hi.x = *(uint32_t*)&h0; hi.y = *(uint32_t*)&h1;
    lo.x = *(uint32_t*)&l0; lo.y = *(uint32_t*)&l1;
}

// ---------------------------------------------------------------------------
// C[8192,1024] = A[8192,1024] @ W[1024,1024]^T + bias  via bf16x3 mma.sync
// CTA: 128x128 tile, 256 threads (8 warps, 2x4 grid of 64x32 warp tiles).
// K staged 64 fp32 at a time -> 4 bf16 tiles {Ah,Al,Bh,Bl}, double buffered.
// Row stride 72 bf16 (144B): (9r+c) mod 8 = (r+c) mod 8 -> ldmatrix
// conflict-free over every 8-row phase.
// ---------------------------------------------------------------------------
#define LDT     72
#define TILE_B  (128 * LDT * 2)     // 18432 B per bf16 tile
#define STAGE_B (4 * TILE_B)        // 73728 B
#define DSMEM_B (2 * STAGE_B)       // 147456 B

__global__ __launch_bounds__(256, 1)
void gemm_bf16x3(const float* __restrict__ A, const float* __restrict__ W,
                 const float* __restrict__ bias, float* __restrict__ C)
{
    extern __shared__ char sm[];
    const uint32_t s0 = smem_u32(sm);

    const int tid  = threadIdx.x;
    const int lane = tid & 31;
    const int wid  = tid >> 5;
    const int bm = blockIdx.y * 128;
    const int bn = blockIdx.x * 128;
    const int wm = (wid >> 2) * 64;     // warp row offset in tile
    const int wn = (wid & 3) * 32;      // warp col offset in tile

    float acc[4][4][4];
#pragma unroll
    for (int i = 0; i < 4; i++)
#pragma unroll
        for (int j = 0; j < 4; j++)
#pragma unroll
            for (int q = 0; q < 4; q++) acc[i][j][q] = 0.f;

    // ldmatrix source addresses (within a tile, before tile/stage base)
    const uint32_t offA = (uint32_t)(lane & 15) * 144 + (uint32_t)(lane >> 4) * 16;
    const uint32_t offB = (uint32_t)((lane & 7) + ((lane >> 4) & 1) * 8) * 144
                        + (uint32_t)((lane >> 3) & 1) * 16;

    float4 av[8], bv[8];

    // ---- prologue: load + store stage 0
#pragma unroll
    for (int j = 0; j < 8; j++) {
        int i = tid + j * 256;           // 0..2047
        int row = i >> 4, c4 = i & 15;
        av[j] = *(const float4*)(A + (size_t)(bm + row) * D_MODEL + c4 * 4);
        bv[j] = *(const float4*)(W + (size_t)(bn + row) * D_MODEL + c4 * 4);
    }
    {
        char* stg = sm;                  // buffer 0
#pragma unroll
        for (int j = 0; j < 8; j++) {
            int i = tid + j * 256;
            int row = i >> 4, c4 = i & 15;
            uint32_t ad = (uint32_t)(row * 144 + c4 * 8);
            uint2 hi, lo;
            split_f4(av[j], hi, lo);
            *(uint2*)(stg + 0 * TILE_B + ad) = hi;
            *(uint2*)(stg + 1 * TILE_B + ad) = lo;
            split_f4(bv[j], hi, lo);
            *(uint2*)(stg + 2 * TILE_B + ad) = hi;
            *(uint2*)(stg + 3 * TILE_B + ad) = lo;
        }
    }
    __syncthreads();

    for (int kt = 0; kt < 16; kt++) {
        // prefetch next stage's gmem into registers
        if (kt < 15) {
#pragma unroll
            for (int j = 0; j < 8; j++) {
                int i = tid + j * 256;
                int row = i >> 4, c4 = i & 15;
                const float* Ap = A + (size_t)(bm + row) * D_MODEL
                                  + (kt + 1) * 64 + c4 * 4;
                const float* Wp = W + (size_t)(bn + row) * D_MODEL
                                  + (kt + 1) * 64 + c4 * 4;
                av[j] = *(const float4*)Ap;
                bv[j] = *(const float4*)Wp;
            }
        }

        // compute on current buffer
        const uint32_t sb = s0 + (uint32_t)(kt & 1) * STAGE_B;
        const uint32_t sAh = sb, sAl = sb + TILE_B;
        const uint32_t sBh = sb + 2 * TILE_B, sBl = sb + 3 * TILE_B;

#pragma unroll
        for (int ks = 0; ks < 4; ks++) {
            uint32_t ah[4][4], al[4][4], bh[2][4], bl[2][4];
            const uint32_t ka = (uint32_t)ks * 32;
#pragma unroll
            for (int mt = 0; mt < 4; mt++) {
                uint32_t ra = (uint32_t)((wm + mt * 16) * 144) + offA + ka;
                ldm_x4(ah[mt], sAh + ra);
                ldm_x4(al[mt], sAl + ra);
            }
#pragma unroll
            for (int p = 0; p < 2; p++) {
                uint32_t rb = (uint32_t)((wn + p * 16) * 144) + offB + ka;
                ldm_x4(bh[p], sBh + rb);
                ldm_x4(bl[p], sBl + rb);
            }
#pragma unroll
            for (int mt = 0; mt < 4; mt++)
#pragma unroll
                for (int nt = 0; nt < 4; nt++) {
                    uint32_t h0 = bh[nt >> 1][(nt & 1) * 2];
                    uint32_t h1 = bh[nt >> 1][(nt & 1) * 2 + 1];
                    uint32_t l0 = bl[nt >> 1][(nt & 1) * 2];
                    uint32_t l1 = bl[nt >> 1][(nt & 1) * 2 + 1];
                    mma16816(acc[mt][nt], ah[mt], h0, h1);   // hi*hi
                    mma16816(acc[mt][nt], ah[mt], l0, l1);   // hi*lo
                    mma16816(acc[mt][nt], al[mt], h0, h1);   // lo*hi
                }
        }

        // store next stage
        if (kt < 15) {
            char* stg = sm + ((kt + 1) & 1) * STAGE_B;
#pragma unroll
            for (int j = 0; j < 8; j++) {
                int i = tid + j * 256;
                int row = i >> 4, c4 = i & 15;
                uint32_t ad = (uint32_t)(row * 144 + c4 * 8);
                uint2 hi, lo;
                split_f4(av[j], hi, lo);
                *(uint2*)(stg + 0 * TILE_B + ad) = hi;
                *(uint2*)(stg + 1 * TILE_B + ad) = lo;
                split_f4(bv[j], hi, lo);
                *(uint2*)(stg + 2 * TILE_B + ad) = hi;
                *(uint2*)(stg + 3 * TILE_B + ad) = lo;
            }
        }
        __syncthreads();
    }

    // ---- epilogue: acc -> C with bias
#pragma unroll
    for (int mt = 0; mt < 4; mt++) {
        int row0 = bm + wm + mt * 16 + (lane >> 2);
#pragma unroll
        for (int nt = 0; nt < 4; nt++) {
            int col = bn + wn + nt * 8 + (lane & 3) * 2;
            float2 b2 = *(const float2*)&bias[col];
            float2 o0 = make_float2(acc[mt][nt][0] + b2.x, acc[mt][nt][1] + b2.y);
            float2 o1 = make_float2(acc[mt][nt][2] + b2.x, acc[mt][nt][3] + b2.y);
            *(float2*)(C + (size_t)row0 * D_MODEL + col) = o0;
            *(float2*)(C + (size_t)(row0 + 8) * D_MODEL + col) = o1;
        }
    }
}

// ---------------------------------------------------------------------------
// Flash attention, fp32 (unchanged)
// ---------------------------------------------------------------------------
__global__ __launch_bounds__(128)
void attn_fwd(const float* __restrict__ Qg, const float* __restrict__ Kg,
              const float* __restrict__ Vg, float* __restrict__ Og)
{
    __shared__ float Qt[64][68];
    __shared__ float Kt[64][36];
    __shared__ float Vs[32][64];
    __shared__ float Pt[32][68];

    const int t  = threadIdx.x;
    const int mt = blockIdx.x;
    const int h  = blockIdx.y;
    const int b  = blockIdx.z;
    const int cg = t & 7;
    const int rg = t >> 3;
    const int tm0 = rg * 4;
    const int tnS = cg * 4;
    const int td0 = cg * 8;

    const float* Qb = Qg + ((size_t)(b * SEQ) + mt * 64) * D_MODEL + h * HDIM;
    const float* Kb = Kg + (size_t)(b * SEQ) * D_MODEL + h * HDIM;
    const float* Vb = Vg + (size_t)(b * SEQ) * D_MODEL + h * HDIM;

    for (int i = t; i < 64 * 16; i += 128) {
        int m = i >> 4, f4 = i & 15;
        float4 v = *(const float4*)(Qb + (size_t)m * D_MODEL + f4 * 4);
        Qt[f4 * 4 + 0][m] = v.x; Qt[f4 * 4 + 1][m] = v.y;
        Qt[f4 * 4 + 2][m] = v.z; Qt[f4 * 4 + 3][m] = v.w;
    }

    float mrow[4], lrow[4], o[4][8];
#pragma unroll
    for (int r = 0; r < 4; r++) {
        mrow[r] = -1e30f; lrow[r] = 0.f;
#pragma unroll
        for (int d = 0; d < 8; d++) o[r][d] = 0.f;
    }

    const float SC = 0.125f;

    for (int kt = 0; kt < SEQ / 32; kt++) {
        __syncthreads();
        const float* Kp = Kb + (size_t)kt * 32 * D_MODEL;
        const float* Vp = Vb + (size_t)kt * 32 * D_MODEL;
        for (int i = t; i < 32 * 16; i += 128) {
            int n = i >> 4, f4 = i & 15;
            float4 kv = *(const float4*)(Kp + (size_t)n * D_MODEL + f4 * 4);
            Kt[f4 * 4 + 0][n] = kv.x; Kt[f4 * 4 + 1][n] = kv.y;
            Kt[f4 * 4 + 2][n] = kv.z; Kt[f4 * 4 + 3][n] = kv.w;
            float4 vv = *(const float4*)(Vp + (size_t)n * D_MODEL + f4 * 4);
            *(float4*)&Vs[n][f4 * 4] = vv;
        }
        __syncthreads();

        float s[4][4];
#pragma unroll
        for (int r = 0; r < 4; r++)
#pragma unroll
            for (int j = 0; j < 4; j++) s[r][j] = 0.f;

#pragma unroll 8
        for (int d = 0; d < 64; d++) {
            float a[4], bb[4];
            *(float4*)a  = *(const float4*)&Qt[d][tm0];
            *(float4*)bb = *(const float4*)&Kt[d][tnS];
#pragma unroll
            for (int r = 0; r < 4; r++)
#pragma unroll
                for (int j = 0; j < 4; j++)
                    s[r][j] = fmaf(a[r], bb[j], s[r][j]);
        }

        float p[4][4];
#pragma unroll
        for (int r = 0; r < 4; r++) {
            float mx = fmaxf(fmaxf(s[r][0], s[r][1]), fmaxf(s[r][2], s[r][3]));
            mx = fmaxf(mx, __shfl_xor_sync(0xffffffffu, mx, 1));
            mx = fmaxf(mx, __shfl_xor_sync(0xffffffffu, mx, 2));
            mx = fmaxf(mx, __shfl_xor_sync(0xffffffffu, mx, 4));
            float mn   = fmaxf(mrow[r], mx);
            float corr = __expf((mrow[r] - mn) * SC);
            mrow[r] = mn;
            float rs = 0.f;
#pragma unroll
            for (int j = 0; j < 4; j++) {
                p[r][j] = __expf((s[r][j] - mn) * SC);
                rs += p[r][j];
            }
            rs += __shfl_xor_sync(0xffffffffu, rs, 1);
            rs += __shfl_xor_sync(0xffffffffu, rs, 2);
            rs += __shfl_xor_sync(0xffffffffu, rs, 4);
            lrow[r] = lrow[r] * corr + rs;
#pragma unroll
            for (int d = 0; d < 8; d++) o[r][d] *= corr;
        }

#pragma unroll
        for (int j = 0; j < 4; j++)
#pragma unroll
            for (int r = 0; r < 4; r++)
                Pt[tnS + j][tm0 + r] = p[r][j];
        __syncthreads();

#pragma unroll 4
        for (int j = 0; j < 32; j++) {
            float a[4], vv[8];
            *(float4*)a      = *(const float4*)&Pt[j][tm0];
            *(float4*)&vv[0] = *(const float4*)&Vs[j][td0];
            *(float4*)&vv[4] = *(const float4*)&Vs[j][td0 + 4];
#pragma unroll
            for (int r = 0; r < 4; r++)
#pragma unroll
                for (int d = 0; d < 8; d++)
                    o[r][d] = fmaf(a[r], vv[d], o[r][d]);
        }
    }

#pragma unroll
    for (int r = 0; r < 4; r++) {
        float inv = 1.f / lrow[r];
        float out[8];
#pragma unroll
        for (int d = 0; d < 8; d++) out[d] = o[r][d] * inv;
        float* Op = Og + ((size_t)(b * SEQ) + mt * 64 + tm0 + r) * D_MODEL
                    + h * HDIM + td0;
        *(float4*)&Op[0] = *(const float4*)&out[0];
        *(float4*)&Op[4] = *(const float4*)&out[4];
    }
}

// ---------------------------------------------------------------------------
extern "C" void kernel_launch(void* const* d_in, const int* in_sizes, int n_in,
                              void* d_out, int out_size)
{
    const float* q  = (const float*)d_in[0];
    const float* k  = (const float*)d_in[1];
    const float* v  = (const float*)d_in[2];
    const float* Wq = (const float*)d_in[3];
    const float* bq = (const float*)d_in[4];
    const float* Wk = (const float*)d_in[5];
    const float* bk = (const float*)d_in[6];
    const float* Wv = (const float*)d_in[7];
    const float* bv = (const float*)d_in[8];
    const float* Wo = (const float*)d_in[9];
    const float* bo = (const float*)d_in[10];
    float* out = (float*)d_out;

    float *gq, *gk, *gv, *ga;
    cudaGetSymbolAddress((void**)&gq, g_q);
    cudaGetSymbolAddress((void**)&gk, g_k);
    cudaGetSymbolAddress((void**)&gv, g_v);
    cudaGetSymbolAddress((void**)&ga, g_att);

    cudaFuncSetAttribute(gemm_bf16x3,
                         cudaFuncAttributeMaxDynamicSharedMemorySize, DSMEM_B);

    dim3 ggrid(D_MODEL / 128, NTOK / 128);   // (8, 64)
    gemm_bf16x3<<<ggrid, 256, DSMEM_B>>>(q, Wq, bq, gq);
    gemm_bf16x3<<<ggrid, 256, DSMEM_B>>>(k, Wk, bk, gk);
    gemm_bf16x3<<<ggrid, 256, DSMEM_B>>>(v, Wv, bv, gv);

    attn_fwd<<<dim3(SEQ / 64, NHEAD, BATCH), 128>>>(gq, gk, gv, ga);

    gemm_bf16x3<<<ggrid, 256, DSMEM_B>>>(ga, Wo, bo, out);
}

// round 4
// speedup vs baseline: 3.5121x; 2.4371x over previous
#include <cuda_runtime.h>
#include <cuda_bf16.h>
#include <cstdint>

#define D_MODEL 1024
#define NHEAD   16
#define HDIM    64
#define BATCH   4
#define SEQ     2048
#define NTOK    (BATCH*SEQ)

// Scratch (allocation-free per harness rules)
__device__ float g_q[(size_t)NTOK * D_MODEL];
__device__ float g_k[(size_t)NTOK * D_MODEL];
__device__ float g_v[(size_t)NTOK * D_MODEL];
__device__ float g_att[(size_t)NTOK * D_MODEL];

// ---------------------------------------------------------------------------
// helpers
// ---------------------------------------------------------------------------
__device__ __forceinline__ uint32_t smem_u32(const void* p) {
    uint32_t a;
    asm("{ .reg .u64 t; cvta.to.shared.u64 t, %1; cvt.u32.u64 %0, t; }"
        : "=r"(a) : "l"(p));
    return a;
}
__device__ __forceinline__ void ldm_x4(uint32_t r[4], uint32_t addr) {
    asm volatile("ldmatrix.sync.aligned.m8n8.x4.shared.b16 {%0,%1,%2,%3}, [%4];"
                 : "=r"(r[0]), "=r"(r[1]), "=r"(r[2]), "=r"(r[3]) : "r"(addr));
}
__device__ __forceinline__ void ldm_x4_t(uint32_t r[4], uint32_t addr) {
    asm volatile("ldmatrix.sync.aligned.m8n8.x4.trans.shared.b16 {%0,%1,%2,%3}, [%4];"
                 : "=r"(r[0]), "=r"(r[1]), "=r"(r[2]), "=r"(r[3]) : "r"(addr));
}
__device__ __forceinline__ void mma16816(float c[4], const uint32_t a[4],
                                         uint32_t b0, uint32_t b1) {
    asm volatile(
        "mma.sync.aligned.m16n8k16.row.col.f32.bf16.bf16.f32 "
        "{%0,%1,%2,%3}, {%4,%5,%6,%7}, {%8,%9}, {%0,%1,%2,%3};"
        : "+f"(c[0]), "+f"(c[1]), "+f"(c[2]), "+f"(c[3])
        : "r"(a[0]), "r"(a[1]), "r"(a[2]), "r"(a[3]), "r"(b0), "r"(b1));
}
// split pair of fp32 into packed bf16x2 hi and bf16x2 lo
__device__ __forceinline__ void split2(float f0, float f1,
                                       uint32_t& hi, uint32_t& lo) {
    __nv_bfloat162 h = __float22bfloat162_rn(make_float2(f0, f1));
    float2 hf = make_float2(__low2float(h), __high2float(h));
    __nv_bfloat162 l = __float22bfloat162_rn(make_float2(f0 - hf.x, f1 - hf.y));
    hi = *(uint32_t*)&h; lo = *(uint32_t*)&l;
}
// split one float4 into packed-hi (uint2) and packed-lo (uint2) bf16x4
__device__ __forceinline__ void split_f4(float4 v, uint2& hi, uint2& lo) {
    split2(v.x, v.y, hi.x, lo.x);
    split2(v.z, v.w, hi.y, lo.y);
}

// ---------------------------------------------------------------------------
// GEMM: C[8192,1024] = A @ W^T + bias  via bf16x3 mma.sync  (unchanged R3)
// ---------------------------------------------------------------------------
#define LDT     72
#define TILE_B  (128 * LDT * 2)
#define STAGE_B (4 * TILE_B)
#define DSMEM_B (2 * STAGE_B)

__global__ __launch_bounds__(256, 1)
void gemm_bf16x3(const float* __restrict__ A, const float* __restrict__ W,
                 const float* __restrict__ bias, float* __restrict__ C)
{
    extern __shared__ char sm[];
    const uint32_t s0 = smem_u32(sm);

    const int tid  = threadIdx.x;
    const int lane = tid & 31;
    const int wid  = tid >> 5;
    const int bm = blockIdx.y * 128;
    const int bn = blockIdx.x * 128;
    const int wm = (wid >> 2) * 64;
    const int wn = (wid & 3) * 32;

    float acc[4][4][4];
#pragma unroll
    for (int i = 0; i < 4; i++)
#pragma unroll
        for (int j = 0; j < 4; j++)
#pragma unroll
            for (int q = 0; q < 4; q++) acc[i][j][q] = 0.f;

    const uint32_t offA = (uint32_t)(lane & 15) * 144 + (uint32_t)(lane >> 4) * 16;
    const uint32_t offB = (uint32_t)((lane & 7) + ((lane >> 4) & 1) * 8) * 144
                        + (uint32_t)((lane >> 3) & 1) * 16;

    float4 av[8], bv[8];
#pragma unroll
    for (int j = 0; j < 8; j++) {
        int i = tid + j * 256;
        int row = i >> 4, c4 = i & 15;
        av[j] = *(const float4*)(A + (size_t)(bm + row) * D_MODEL + c4 * 4);
        bv[j] = *(const float4*)(W + (size_t)(bn + row) * D_MODEL + c4 * 4);
    }
    {
        char* stg = sm;
#pragma unroll
        for (int j = 0; j < 8; j++) {
            int i = tid + j * 256;
            int row = i >> 4, c4 = i & 15;
            uint32_t ad = (uint32_t)(row * 144 + c4 * 8);
            uint2 hi, lo;
            split_f4(av[j], hi, lo);
            *(uint2*)(stg + 0 * TILE_B + ad) = hi;
            *(uint2*)(stg + 1 * TILE_B + ad) = lo;
            split_f4(bv[j], hi, lo);
            *(uint2*)(stg + 2 * TILE_B + ad) = hi;
            *(uint2*)(stg + 3 * TILE_B + ad) = lo;
        }
    }
    __syncthreads();

    for (int kt = 0; kt < 16; kt++) {
        if (kt < 15) {
#pragma unroll
            for (int j = 0; j < 8; j++) {
                int i = tid + j * 256;
                int row = i >> 4, c4 = i & 15;
                av[j] = *(const float4*)(A + (size_t)(bm + row) * D_MODEL
                                         + (kt + 1) * 64 + c4 * 4);
                bv[j] = *(const float4*)(W + (size_t)(bn + row) * D_MODEL
                                         + (kt + 1) * 64 + c4 * 4);
            }
        }

        const uint32_t sb = s0 + (uint32_t)(kt & 1) * STAGE_B;
        const uint32_t sAh = sb, sAl = sb + TILE_B;
        const uint32_t sBh = sb + 2 * TILE_B, sBl = sb + 3 * TILE_B;

#pragma unroll
        for (int ks = 0; ks < 4; ks++) {
            uint32_t ah[4][4], al[4][4], bh[2][4], bl[2][4];
            const uint32_t ka = (uint32_t)ks * 32;
#pragma unroll
            for (int mt = 0; mt < 4; mt++) {
                uint32_t ra = (uint32_t)((wm + mt * 16) * 144) + offA + ka;
                ldm_x4(ah[mt], sAh + ra);
                ldm_x4(al[mt], sAl + ra);
            }
#pragma unroll
            for (int p = 0; p < 2; p++) {
                uint32_t rb = (uint32_t)((wn + p * 16) * 144) + offB + ka;
                ldm_x4(bh[p], sBh + rb);
                ldm_x4(bl[p], sBl + rb);
            }
#pragma unroll
            for (int mt = 0; mt < 4; mt++)
#pragma unroll
                for (int nt = 0; nt < 4; nt++) {
                    uint32_t h0 = bh[nt >> 1][(nt & 1) * 2];
                    uint32_t h1 = bh[nt >> 1][(nt & 1) * 2 + 1];
                    uint32_t l0 = bl[nt >> 1][(nt & 1) * 2];
                    uint32_t l1 = bl[nt >> 1][(nt & 1) * 2 + 1];
                    mma16816(acc[mt][nt], ah[mt], h0, h1);
                    mma16816(acc[mt][nt], ah[mt], l0, l1);
                    mma16816(acc[mt][nt], al[mt], h0, h1);
                }
        }

        if (kt < 15) {
            char* stg = sm + ((kt + 1) & 1) * STAGE_B;
#pragma unroll
            for (int j = 0; j < 8; j++) {
                int i = tid + j * 256;
                int row = i >> 4, c4 = i & 15;
                uint32_t ad = (uint32_t)(row * 144 + c4 * 8);
                uint2 hi, lo;
                split_f4(av[j], hi, lo);
                *(uint2*)(stg + 0 * TILE_B + ad) = hi;
                *(uint2*)(stg + 1 * TILE_B + ad) = lo;
                split_f4(bv[j], hi, lo);
                *(uint2*)(stg + 2 * TILE_B + ad) = hi;
                *(uint2*)(stg + 3 * TILE_B + ad) = lo;
            }
        }
        __syncthreads();
    }

#pragma unroll
    for (int mt = 0; mt < 4; mt++) {
        int row0 = bm + wm + mt * 16 + (lane >> 2);
#pragma unroll
        for (int nt = 0; nt < 4; nt++) {
            int col = bn + wn + nt * 8 + (lane & 3) * 2;
            float2 b2 = *(const float2*)&bias[col];
            float2 o0 = make_float2(acc[mt][nt][0] + b2.x, acc[mt][nt][1] + b2.y);
            float2 o1 = make_float2(acc[mt][nt][2] + b2.x, acc[mt][nt][3] + b2.y);
            *(float2*)(C + (size_t)row0 * D_MODEL + col) = o0;
            *(float2*)(C + (size_t)(row0 + 8) * D_MODEL + col) = o1;
        }
    }
}

// ---------------------------------------------------------------------------
// Flash attention via bf16x3 mma.sync.
// CTA: 128 q-rows x (b,h). 4 warps, each 32 q-rows (2 m16 tiles). BN=64 KV.
// smem: Qhi/Qlo [128][72]bf16 resident, Khi/Klo/Vhi/Vlo [64][72] per tile.
// Row stride 144B -> conflict-free ldmatrix. P stays in registers.
// ---------------------------------------------------------------------------
#define AQH 0
#define AQL 18432
#define AKH 36864
#define AKL 46080
#define AVH 55296
#define AVL 64512
#define A_SMEM 73728

__global__ __launch_bounds__(128, 1)
void attn_mma(const float* __restrict__ Qg, const float* __restrict__ Kg,
              const float* __restrict__ Vg, float* __restrict__ Og)
{
    extern __shared__ char sm[];
    const uint32_t s0 = smem_u32(sm);

    const int tid  = threadIdx.x;
    const int lane = tid & 31;
    const int wid  = tid >> 5;
    const int qt = blockIdx.x;          // 16 q-tiles
    const int bh = blockIdx.y;          // 64 (b,h)
    const int b = bh >> 4, h = bh & 15;

    const size_t tok0 = (size_t)b * SEQ + qt * 128;
    const float* Qb = Qg + tok0 * D_MODEL + h * 64;
    const float* Kb = Kg + (size_t)b * SEQ * D_MODEL + h * 64;
    const float* Vb = Vg + (size_t)b * SEQ * D_MODEL + h * 64;

    // per-lane ldmatrix offsets
    const uint32_t laneA = (uint32_t)(((lane >> 3) & 1) * 8 + (lane & 7)) * 144
                         + (uint32_t)(lane >> 4) * 16;   // A frags (Q) and V trans
    const uint32_t laneB = (uint32_t)((lane >> 4) * 8 + (lane & 7)) * 144
                         + (uint32_t)((lane >> 3) & 1) * 16;  // B frags (K)
    const uint32_t wq = (uint32_t)wid * 32 * 144;

    // load Q tile (128 x 64 fp32), split into Qhi/Qlo
#pragma unroll
    for (int j = 0; j < 16; j++) {
        int i = tid + j * 128;
        int row = i >> 4, c4 = i & 15;
        float4 v = *(const float4*)(Qb + (size_t)row * D_MODEL + c4 * 4);
        uint2 hi, lo;
        split_f4(v, hi, lo);
        uint32_t ad = (uint32_t)(row * 144 + c4 * 8);
        *(uint2*)(sm + AQH + ad) = hi;
        *(uint2*)(sm + AQL + ad) = lo;
    }

    float o[2][8][4];
#pragma unroll
    for (int mt = 0; mt < 2; mt++)
#pragma unroll
        for (int dn = 0; dn < 8; dn++)
#pragma unroll
            for (int q = 0; q < 4; q++) o[mt][dn][q] = 0.f;
    float mrow[4] = {-1e30f, -1e30f, -1e30f, -1e30f};
    float lrow[4] = {0.f, 0.f, 0.f, 0.f};

    const float SC = 0.125f;

    for (int kt = 0; kt < SEQ / 64; kt++) {
        __syncthreads();   // previous tile's smem reads complete
        // load K,V tiles (64 x 64 fp32 each), split
#pragma unroll
        for (int j = 0; j < 8; j++) {
            int i = tid + j * 128;
            int row = i >> 4, c4 = i & 15;
            size_t gro = (size_t)(kt * 64 + row) * D_MODEL + c4 * 4;
            uint32_t ad = (uint32_t)(row * 144 + c4 * 8);
            uint2 hi, lo;
            split_f4(*(const float4*)(Kb + gro), hi, lo);
            *(uint2*)(sm + AKH + ad) = hi;
            *(uint2*)(sm + AKL + ad) = lo;
            split_f4(*(const float4*)(Vb + gro), hi, lo);
            *(uint2*)(sm + AVH + ad) = hi;
            *(uint2*)(sm + AVL + ad) = lo;
        }
        __syncthreads();

        // ---- S = Q @ K^T (3-pass split)
        float s[2][8][4];
#pragma unroll
        for (int mt = 0; mt < 2; mt++)
#pragma unroll
            for (int nt = 0; nt < 8; nt++)
#pragma unroll
                for (int q = 0; q < 4; q++) s[mt][nt][q] = 0.f;

#pragma unroll
        for (int k = 0; k < 4; k++) {
            uint32_t bhf[4][4], blf[4][4];
#pragma unroll
            for (int np = 0; np < 4; np++) {
                uint32_t rb = (uint32_t)(np * 16 * 144) + k * 32 + laneB;
                ldm_x4(bhf[np], s0 + AKH + rb);
                ldm_x4(blf[np], s0 + AKL + rb);
            }
#pragma unroll
            for (int mt = 0; mt < 2; mt++) {
                uint32_t ah[4], al[4];
                uint32_t ra = wq + (uint32_t)(mt * 16 * 144) + k * 32 + laneA;
                ldm_x4(ah, s0 + AQH + ra);
                ldm_x4(al, s0 + AQL + ra);
#pragma unroll
                for (int nt = 0; nt < 8; nt++) {
                    uint32_t h0 = bhf[nt >> 1][(nt & 1) * 2];
                    uint32_t h1 = bhf[nt >> 1][(nt & 1) * 2 + 1];
                    uint32_t l0 = blf[nt >> 1][(nt & 1) * 2];
                    uint32_t l1 = blf[nt >> 1][(nt & 1) * 2 + 1];
                    mma16816(s[mt][nt], ah, h0, h1);
                    mma16816(s[mt][nt], ah, l0, l1);
                    mma16816(s[mt][nt], al, h0, h1);
                }
            }
        }

        // ---- online softmax in fragments (rows: rr = mt*2 + hilo)
        float corr[4];
#pragma unroll
        for (int rr = 0; rr < 4; rr++) {
            int mt = rr >> 1, c0 = (rr & 1) * 2;
            float mx = -1e30f;
#pragma unroll
            for (int nt = 0; nt < 8; nt++)
                mx = fmaxf(mx, fmaxf(s[mt][nt][c0], s[mt][nt][c0 + 1]));
            mx = fmaxf(mx, __shfl_xor_sync(0xffffffffu, mx, 1));
            mx = fmaxf(mx, __shfl_xor_sync(0xffffffffu, mx, 2));
            float mn = fmaxf(mrow[rr], mx);
            corr[rr] = __expf((mrow[rr] - mn) * SC);
            mrow[rr] = mn;
            float rs = 0.f;
#pragma unroll
            for (int nt = 0; nt < 8; nt++) {
                float e0 = __expf((s[mt][nt][c0] - mn) * SC);
                float e1 = __expf((s[mt][nt][c0 + 1] - mn) * SC);
                s[mt][nt][c0] = e0; s[mt][nt][c0 + 1] = e1;
                rs += e0 + e1;
            }
            rs += __shfl_xor_sync(0xffffffffu, rs, 1);
            rs += __shfl_xor_sync(0xffffffffu, rs, 2);
            lrow[rr] = lrow[rr] * corr[rr] + rs;
        }
#pragma unroll
        for (int mt = 0; mt < 2; mt++)
#pragma unroll
            for (int dn = 0; dn < 8; dn++) {
                o[mt][dn][0] *= corr[mt * 2];
                o[mt][dn][1] *= corr[mt * 2];
                o[mt][dn][2] *= corr[mt * 2 + 1];
                o[mt][dn][3] *= corr[mt * 2 + 1];
            }

        // ---- O += P @ V (3-pass split, P packed on the fly)
#pragma unroll
        for (int kk = 0; kk < 4; kk++) {
            uint32_t vhf[4][4], vlf[4][4];
#pragma unroll
            for (int dp = 0; dp < 4; dp++) {
                uint32_t rv = (uint32_t)(kk * 16 * 144) + dp * 32 + laneA;
                ldm_x4_t(vhf[dp], s0 + AVH + rv);
                ldm_x4_t(vlf[dp], s0 + AVL + rv);
            }
#pragma unroll
            for (int mt = 0; mt < 2; mt++) {
                uint32_t ah[4], al[4];
                split2(s[mt][2 * kk][0],     s[mt][2 * kk][1],     ah[0], al[0]);
                split2(s[mt][2 * kk][2],     s[mt][2 * kk][3],     ah[1], al[1]);
                split2(s[mt][2 * kk + 1][0], s[mt][2 * kk + 1][1], ah[2], al[2]);
                split2(s[mt][2 * kk + 1][2], s[mt][2 * kk + 1][3], ah[3], al[3]);
#pragma unroll
                for (int dn = 0; dn < 8; dn++) {
                    uint32_t h0 = vhf[dn >> 1][(dn & 1) * 2];
                    uint32_t h1 = vhf[dn >> 1][(dn & 1) * 2 + 1];
                    uint32_t l0 = vlf[dn >> 1][(dn & 1) * 2];
                    uint32_t l1 = vlf[dn >> 1][(dn & 1) * 2 + 1];
                    mma16816(o[mt][dn], ah, h0, h1);
                    mma16816(o[mt][dn], ah, l0, l1);
                    mma16816(o[mt][dn], al, h0, h1);
                }
            }
        }
    }

    // ---- epilogue
    float inv[4];
#pragma unroll
    for (int rr = 0; rr < 4; rr++) inv[rr] = 1.f / lrow[rr];
#pragma unroll
    for (int mt = 0; mt < 2; mt++) {
        size_t row_lo = tok0 + wid * 32 + mt * 16 + (lane >> 2);
#pragma unroll
        for (int dn = 0; dn < 8; dn++) {
            int col = h * 64 + dn * 8 + (lane & 3) * 2;
            float2 o0 = make_float2(o[mt][dn][0] * inv[mt * 2],
                                    o[mt][dn][1] * inv[mt * 2]);
            float2 o1 = make_float2(o[mt][dn][2] * inv[mt * 2 + 1],
                                    o[mt][dn][3] * inv[mt * 2 + 1]);
            *(float2*)(Og + row_lo * D_MODEL + col) = o0;
            *(float2*)(Og + (row_lo + 8) * D_MODEL + col) = o1;
        }
    }
}

// ---------------------------------------------------------------------------
extern "C" void kernel_launch(void* const* d_in, const int* in_sizes, int n_in,
                              void* d_out, int out_size)
{
    const float* q  = (const float*)d_in[0];
    const float* k  = (const float*)d_in[1];
    const float* v  = (const float*)d_in[2];
    const float* Wq = (const float*)d_in[3];
    const float* bq = (const float*)d_in[4];
    const float* Wk = (const float*)d_in[5];
    const float* bk = (const float*)d_in[6];
    const float* Wv = (const float*)d_in[7];
    const float* bv = (const float*)d_in[8];
    const float* Wo = (const float*)d_in[9];
    const float* bo = (const float*)d_in[10];
    float* out = (float*)d_out;

    float *gq, *gk, *gv, *ga;
    cudaGetSymbolAddress((void**)&gq, g_q);
    cudaGetSymbolAddress((void**)&gk, g_k);
    cudaGetSymbolAddress((void**)&gv, g_v);
    cudaGetSymbolAddress((void**)&ga, g_att);

    cudaFuncSetAttribute(gemm_bf16x3,
                         cudaFuncAttributeMaxDynamicSharedMemorySize, DSMEM_B);
    cudaFuncSetAttribute(attn_mma,
                         cudaFuncAttributeMaxDynamicSharedMemorySize, A_SMEM);

    dim3 ggrid(D_MODEL / 128, NTOK / 128);   // (8, 64)
    gemm_bf16x3<<<ggrid, 256, DSMEM_B>>>(q, Wq, bq, gq);
    gemm_bf16x3<<<ggrid, 256, DSMEM_B>>>(k, Wk, bk, gk);
    gemm_bf16x3<<<ggrid, 256, DSMEM_B>>>(v, Wv, bv, gv);

    attn_mma<<<dim3(SEQ / 128, BATCH * NHEAD), 128, A_SMEM>>>(gq, gk, gv, ga);

    gemm_bf16x3<<<ggrid, 256, DSMEM_B>>>(ga, Wo, bo, out);
}